// round 1
// baseline (speedup 1.0000x reference)
#include <cuda_runtime.h>

#define NBATCH 16
#define PPIX   (640*640)      // 409600 pixels per image
#define NCHUNK (PPIX/4)       // 102400 4-pixel chunks per image

// ---------------- device-global scratch (no allocations allowed) -------------
__device__ float g_sum[NBATCH][8][4];   // kernel-region emb sums per label
__device__ float g_ck [NBATCH][8];      // kernel-region counts per label
__device__ float g_ci [NBATCH][8];      // instance-region counts per label
__device__ float g_term[NBATCH][8];     // aggregation log-term sums per label
__device__ float g_mu [NBATCH][8][4];   // per-label means
__device__ float g_misc[NBATCH];        // l_dis + l_reg per batch

__device__ __forceinline__ float wredf(float v) {
#pragma unroll
    for (int o = 16; o; o >>= 1) v += __shfl_xor_sync(0xffffffffu, v, o);
    return v;
}

// ---------------- kernel 0: zero accumulators --------------------------------
__global__ void k_zero() {
    int t = threadIdx.x;
    if (t < 512) (&g_sum[0][0][0])[t] = 0.f;
    if (t < 128) {
        (&g_ck[0][0])[t]   = 0.f;
        (&g_ci[0][0])[t]   = 0.f;
        (&g_term[0][0])[t] = 0.f;
    }
}

// ---------------- pass 1: segment sums/counts --------------------------------
#define PASS1_PX(LAB, KV, TV, EV)                                         \
    {                                                                     \
        int  la = ((TV) > 0.5f) ? (LAB) : 0;                              \
        bool kk = ((KV) > 0.5f);                                          \
        _Pragma("unroll")                                                 \
        for (int l = 1; l < 8; l++) {                                     \
            if (kk && la == l) {                                          \
                s[l-1][0] += (EV).x; s[l-1][1] += (EV).y;                 \
                s[l-1][2] += (EV).z; s[l-1][3] += (EV).w;                 \
                ck[l-1] += 1.f;                                           \
            }                                                             \
        }                                                                 \
        _Pragma("unroll")                                                 \
        for (int l = 2; l < 8; l++) {                                     \
            if (la == l) ci[l-2] += 1.f;                                  \
        }                                                                 \
    }

__global__ __launch_bounds__(256)
void k_pass1(const float4* __restrict__ emb, const int4* __restrict__ inst,
             const float4* __restrict__ ker, const float4* __restrict__ tmk) {
    const int b = blockIdx.y;
    float s[7][4], ck[7], ci[6];
#pragma unroll
    for (int l = 0; l < 7; l++) {
        ck[l] = 0.f;
#pragma unroll
        for (int c = 0; c < 4; c++) s[l][c] = 0.f;
    }
#pragma unroll
    for (int l = 0; l < 6; l++) ci[l] = 0.f;

    const size_t base   = (size_t)b * NCHUNK;
    const int    stride = gridDim.x * blockDim.x;
    for (int m = blockIdx.x * blockDim.x + threadIdx.x; m < NCHUNK; m += stride) {
        int4   iv = inst[base + m];
        float4 kv = ker [base + m];
        float4 tv = tmk [base + m];
        const float4* e4 = emb + ((base + (size_t)m) << 2);
        float4 e0 = e4[0], e1 = e4[1], e2 = e4[2], e3 = e4[3];
        PASS1_PX(iv.x, kv.x, tv.x, e0);
        PASS1_PX(iv.y, kv.y, tv.y, e1);
        PASS1_PX(iv.z, kv.z, tv.z, e2);
        PASS1_PX(iv.w, kv.w, tv.w, e3);
    }

    const unsigned lane = threadIdx.x & 31u;
#pragma unroll
    for (int l = 0; l < 7; l++) {
#pragma unroll
        for (int c = 0; c < 4; c++) {
            float v = wredf(s[l][c]);
            if (lane == 0) atomicAdd(&g_sum[b][l + 1][c], v);
        }
        float v = wredf(ck[l]);
        if (lane == 0) atomicAdd(&g_ck[b][l + 1], v);
    }
#pragma unroll
    for (int l = 0; l < 6; l++) {
        float v = wredf(ci[l]);
        if (lane == 0) atomicAdd(&g_ci[b][l + 2], v);
    }
}

// ---------------- mid kernel: mu, discrimination + reg terms -----------------
__global__ void k_mid() {
    __shared__ float4 smu[NBATCH][8];
    int t = threadIdx.x;
    if (t < 128) {
        int b = t >> 3, l = t & 7;
        float4 mu = make_float4(0.f, 0.f, 0.f, 0.f);
        if (l > 0) {
            float c = fmaxf(g_ck[b][l], 1.f);
            mu.x = g_sum[b][l][0] / c;
            mu.y = g_sum[b][l][1] / c;
            mu.z = g_sum[b][l][2] / c;
            mu.w = g_sum[b][l][3] / c;
        }
        smu[b][l] = mu;
        g_mu[b][l][0] = mu.x; g_mu[b][l][1] = mu.y;
        g_mu[b][l][2] = mu.z; g_mu[b][l][3] = mu.w;
    }
    __syncthreads();
    if (t < NBATCH) {
        int b = t;
        float dis = 0.f;
        for (int i = 1; i < 8; i++) {
            float4 a = smu[b][i];
            for (int j = 1; j < 8; j++) {
                if (j == i) continue;
                float4 c = smu[b][j];
                float dx = a.x - c.x, dy = a.y - c.y, dz = a.z - c.z, dw = a.w - c.w;
                float sq = dx*dx + dy*dy + dz*dz + dw*dw;
                float dd = sqrtf(sq);
                float x  = fmaxf(3.0f - dd, 0.f);     // 2*DELTA_D - dd
                dis += __logf(fmaf(x, x, 1.f));
            }
        }
        dis *= (1.0f / 42.0f);
        float reg = 0.f;
        for (int l = 0; l < 8; l++) {
            float4 a = smu[b][l];
            float n = sqrtf(a.x*a.x + a.y*a.y + a.z*a.z + a.w*a.w);
            reg += __logf(n + 1.f);
        }
        reg *= (0.001f / 8.0f);
        g_misc[b] = dis + reg;
    }
}

// ---------------- pass 2: aggregation term -----------------------------------
#define PASS2_PX(LAB, TV, EV)                                             \
    {                                                                     \
        int la = ((TV) > 0.5f) ? (LAB) : 0;                               \
        float4 mm = smu[la & 7];                                          \
        float dx = (EV).x - mm.x, dy = (EV).y - mm.y;                     \
        float dz = (EV).z - mm.z, dw = (EV).w - mm.w;                     \
        float sq = dx*dx + dy*dy + dz*dz + dw*dw;                         \
        float d  = sqrtf(sq);                                             \
        float x  = fmaxf(d - 0.5f, 0.f);                                  \
        float lg = __logf(fmaf(x, x, 1.f));                               \
        _Pragma("unroll")                                                 \
        for (int l = 2; l < 8; l++) {                                     \
            if (la == l) acc[l-2] += lg;                                  \
        }                                                                 \
    }

__global__ __launch_bounds__(256)
void k_pass2(const float4* __restrict__ emb, const int4* __restrict__ inst,
             const float4* __restrict__ tmk) {
    const int b = (NBATCH - 1) - blockIdx.y;       // reverse batch order for L2 reuse
    __shared__ float4 smu[8];
    if (threadIdx.x < 8) {
        int l = threadIdx.x;
        smu[l] = make_float4(g_mu[b][l][0], g_mu[b][l][1], g_mu[b][l][2], g_mu[b][l][3]);
    }
    __syncthreads();

    float acc[6] = {0.f, 0.f, 0.f, 0.f, 0.f, 0.f};
    const size_t base   = (size_t)b * NCHUNK;
    const int    stride = gridDim.x * blockDim.x;
    for (int mi = blockIdx.x * blockDim.x + threadIdx.x; mi < NCHUNK; mi += stride) {
        int m = (NCHUNK - 1) - mi;                 // reverse pixel order for L2 reuse
        int4   iv = inst[base + m];
        float4 tv = tmk [base + m];
        const float4* e4 = emb + ((base + (size_t)m) << 2);
        float4 e0 = e4[0], e1 = e4[1], e2 = e4[2], e3 = e4[3];
        PASS2_PX(iv.x, tv.x, e0);
        PASS2_PX(iv.y, tv.y, e1);
        PASS2_PX(iv.z, tv.z, e2);
        PASS2_PX(iv.w, tv.w, e3);
    }

    const unsigned lane = threadIdx.x & 31u;
#pragma unroll
    for (int l = 0; l < 6; l++) {
        float v = wredf(acc[l]);
        if (lane == 0) atomicAdd(&g_term[b][l + 2], v);
    }
}

// ---------------- finalize ---------------------------------------------------
__global__ void k_fin(float* out) {
    if (threadIdx.x == 0) {
        float tot = 0.f;
        for (int b = 0; b < NBATCH; b++) {
            float la = 0.f;
            for (int l = 2; l < 8; l++)
                la += g_term[b][l] / fmaxf(g_ci[b][l], 1.f);
            tot += la * (1.0f / 6.0f) + g_misc[b];
        }
        out[0] = tot * (1.0f / 16.0f);   // mean over batch, LOSS_WEIGHT = 1
    }
}

// ---------------- launch -----------------------------------------------------
extern "C" void kernel_launch(void* const* d_in, const int* in_sizes, int n_in,
                              void* d_out, int out_size) {
    (void)in_sizes; (void)n_in; (void)out_size;
    const float4* emb  = (const float4*)d_in[0];
    const int4*   inst = (const int4*)  d_in[1];
    const float4* ker  = (const float4*)d_in[2];
    const float4* tmk  = (const float4*)d_in[3];
    float*        out  = (float*)d_out;

    int nsm = 148;
    cudaDeviceGetAttribute(&nsm, cudaDevAttrMultiProcessorCount, 0);
    int occ1 = 0, occ2 = 0;
    cudaOccupancyMaxActiveBlocksPerMultiprocessor(&occ1, k_pass1, 256, 0);
    cudaOccupancyMaxActiveBlocksPerMultiprocessor(&occ2, k_pass2, 256, 0);
    if (occ1 < 1) occ1 = 1;
    if (occ2 < 1) occ2 = 1;
    int gx1 = (occ1 * nsm) / NBATCH; if (gx1 < 1) gx1 = 1;
    int gx2 = (occ2 * nsm) / NBATCH; if (gx2 < 1) gx2 = 1;

    k_zero<<<1, 512>>>();
    k_pass1<<<dim3(gx1, NBATCH), 256>>>(emb, inst, ker, tmk);
    k_mid<<<1, 128>>>();
    k_pass2<<<dim3(gx2, NBATCH), 256>>>(emb, inst, tmk);
    k_fin<<<1, 32>>>(out);
}

// round 2
// speedup vs baseline: 1.6549x; 1.6549x over previous
#include <cuda_runtime.h>

#define NBATCH 16
#define PPIX   (640*640)      // 409600 pixels per image
#define NCHUNK (PPIX/4)       // 102400 4-pixel chunks per image

// ---------------- device-global scratch (no allocations allowed) -------------
__device__ float  g_sum[NBATCH][8][4];   // kernel-region emb sums per label
__device__ float  g_ck [NBATCH][8];      // kernel-region counts per label
__device__ float  g_ci [NBATCH][8];      // instance-region counts per label
__device__ float4 g_mu [NBATCH][8];      // per-label means
__device__ float  g_w  [NBATCH][8];      // per-label aggregation weights
__device__ float  g_misc[NBATCH];        // l_dis + l_reg per batch
__device__ float  g_loss;                // accumulated weighted agg term

__device__ __forceinline__ float wredf(float v) {
#pragma unroll
    for (int o = 16; o; o >>= 1) v += __shfl_xor_sync(0xffffffffu, v, o);
    return v;
}

__device__ __forceinline__ float fsqrt_ap(float x) {
    float r;
    asm("sqrt.approx.f32 %0, %1;" : "=f"(r) : "f"(x));
    return r;
}

// ---------------- kernel 0: zero accumulators --------------------------------
__global__ void k_zero() {
    int t = threadIdx.x;
    if (t < 512) (&g_sum[0][0][0])[t] = 0.f;
    if (t < 128) {
        (&g_ck[0][0])[t] = 0.f;
        (&g_ci[0][0])[t] = 0.f;
    }
    if (t == 0) g_loss = 0.f;
}

// ---------------- pass 1: segment sums/counts (software pipelined) -----------
// packed 8-bit counters: ck0 = labels 1..4, ck1 = labels 5..7,
//                        ci0 = labels 2..5, ci1 = labels 6..7
#define PASS1_PX(LAB, KV, TV, EV)                                          \
    {                                                                      \
        int  la = ((TV) > 0.5f) ? ((LAB) & 7) : 0;                         \
        bool kk = ((KV) > 0.5f);                                           \
        _Pragma("unroll")                                                  \
        for (int l = 1; l < 8; l++) {                                      \
            if (kk && la == l) {                                           \
                s[l-1][0] += (EV).x; s[l-1][1] += (EV).y;                  \
                s[l-1][2] += (EV).z; s[l-1][3] += (EV).w;                  \
                if (l < 5) ck0 += 1u << (8*(l-1));                         \
                else       ck1 += 1u << (8*(l-5));                         \
            }                                                              \
        }                                                                  \
        _Pragma("unroll")                                                  \
        for (int l = 2; l < 8; l++) {                                      \
            if (la == l) {                                                 \
                if (l < 6) ci0 += 1u << (8*(l-2));                         \
                else       ci1 += 1u << (8*(l-6));                         \
            }                                                              \
        }                                                                  \
    }

__global__ __launch_bounds__(256)
void k_pass1(const float4* __restrict__ emb, const int4* __restrict__ inst,
             const float4* __restrict__ ker, const float4* __restrict__ tmk) {
    const int b = blockIdx.y;
    float s[7][4];
#pragma unroll
    for (int l = 0; l < 7; l++)
#pragma unroll
        for (int c = 0; c < 4; c++) s[l][c] = 0.f;
    unsigned ck0 = 0u, ck1 = 0u, ci0 = 0u, ci1 = 0u;

    const size_t base   = (size_t)b * NCHUNK;
    const int    stride = gridDim.x * blockDim.x;
    const int    iters  = NCHUNK / stride;     // exact (grid chosen as divisor)

    int m = blockIdx.x * blockDim.x + threadIdx.x;
    int4   iv = inst[base + m];
    float4 kv = ker [base + m];
    float4 tv = tmk [base + m];
    const float4* ep = emb + ((base + (size_t)m) << 2);
    float4 e0 = ep[0], e1 = ep[1], e2 = ep[2], e3 = ep[3];

    for (int it = 1; it < iters; it++) {
        const int mn = m + stride;
        int4   ivn = inst[base + mn];
        float4 kvn = ker [base + mn];
        float4 tvn = tmk [base + mn];
        const float4* en = emb + ((base + (size_t)mn) << 2);
        float4 n0 = en[0], n1 = en[1], n2 = en[2], n3 = en[3];

        PASS1_PX(iv.x, kv.x, tv.x, e0);
        PASS1_PX(iv.y, kv.y, tv.y, e1);
        PASS1_PX(iv.z, kv.z, tv.z, e2);
        PASS1_PX(iv.w, kv.w, tv.w, e3);

        iv = ivn; kv = kvn; tv = tvn;
        e0 = n0; e1 = n1; e2 = n2; e3 = n3;
        m = mn;
    }
    PASS1_PX(iv.x, kv.x, tv.x, e0);
    PASS1_PX(iv.y, kv.y, tv.y, e1);
    PASS1_PX(iv.z, kv.z, tv.z, e2);
    PASS1_PX(iv.w, kv.w, tv.w, e3);

    const unsigned lane = threadIdx.x & 31u;
#pragma unroll
    for (int l = 0; l < 7; l++)
#pragma unroll
        for (int c = 0; c < 4; c++) {
            float v = wredf(s[l][c]);
            if (lane == 0) atomicAdd(&g_sum[b][l + 1][c], v);
        }
#pragma unroll
    for (int l = 1; l < 8; l++) {
        float cv = (float)((l < 5 ? (ck0 >> (8*(l-1))) : (ck1 >> (8*(l-5)))) & 255u);
        float v = wredf(cv);
        if (lane == 0) atomicAdd(&g_ck[b][l], v);
    }
#pragma unroll
    for (int l = 2; l < 8; l++) {
        float cv = (float)((l < 6 ? (ci0 >> (8*(l-2))) : (ci1 >> (8*(l-6)))) & 255u);
        float v = wredf(cv);
        if (lane == 0) atomicAdd(&g_ci[b][l], v);
    }
}

// ---------------- mid kernel: mu, weights, discrimination + reg --------------
__global__ void k_mid() {
    __shared__ float4 smu[NBATCH][8];
    int t = threadIdx.x;
    if (t < 128) {
        int b = t >> 3, l = t & 7;
        float4 mu = make_float4(0.f, 0.f, 0.f, 0.f);
        if (l > 0) {
            float c = fmaxf(g_ck[b][l], 1.f);
            mu.x = g_sum[b][l][0] / c;
            mu.y = g_sum[b][l][1] / c;
            mu.z = g_sum[b][l][2] / c;
            mu.w = g_sum[b][l][3] / c;
        }
        smu[b][l] = mu;
        g_mu[b][l] = mu;
        // weight = LOSS_WEIGHT / (6 labels * 16 batch * cnt_i), labels 2..7 only
        float w = 0.f;
        if (l >= 2) w = 1.0f / (96.0f * fmaxf(g_ci[b][l], 1.f));
        g_w[b][l] = w;
    }
    __syncthreads();
    if (t < NBATCH) {
        int b = t;
        float dis = 0.f;
        for (int i = 1; i < 8; i++) {
            float4 a = smu[b][i];
            for (int j = 1; j < 8; j++) {
                if (j == i) continue;
                float4 c = smu[b][j];
                float dx = a.x - c.x, dy = a.y - c.y, dz = a.z - c.z, dw = a.w - c.w;
                float sq = dx*dx + dy*dy + dz*dz + dw*dw;
                float dd = sqrtf(sq);
                float x  = fmaxf(3.0f - dd, 0.f);     // 2*DELTA_D - dd
                dis += logf(fmaf(x, x, 1.f));
            }
        }
        dis *= (1.0f / 42.0f);
        float reg = 0.f;
        for (int l = 0; l < 8; l++) {
            float4 a = smu[b][l];
            float n = sqrtf(a.x*a.x + a.y*a.y + a.z*a.z + a.w*a.w);
            reg += logf(n + 1.f);
        }
        reg *= (0.001f / 8.0f);
        g_misc[b] = dis + reg;
    }
}

// ---------------- pass 2: aggregation term (software pipelined) --------------
#define PASS2_PX(LAB, TV, EV, ACC)                                         \
    {                                                                      \
        int la = ((TV) > 0.5f) ? ((LAB) & 7) : 0;                          \
        float4 mm = smu[la];                                               \
        float  w  = sw[la];                                                \
        float dx = (EV).x - mm.x, dy = (EV).y - mm.y;                      \
        float dz = (EV).z - mm.z, dw = (EV).w - mm.w;                      \
        float sq = fmaf(dx, dx, fmaf(dy, dy, fmaf(dz, dz, dw*dw)));       \
        float d  = fsqrt_ap(sq);                                           \
        float x  = fmaxf(d - 0.5f, 0.f);                                   \
        ACC = fmaf(__logf(fmaf(x, x, 1.f)), w, ACC);                       \
    }

__global__ __launch_bounds__(256)
void k_pass2(const float4* __restrict__ emb, const int4* __restrict__ inst,
             const float4* __restrict__ tmk) {
    const int b = blockIdx.y;
    __shared__ float4 smu[8];
    __shared__ float  sw[8];
    if (threadIdx.x < 8) {
        smu[threadIdx.x] = g_mu[b][threadIdx.x];
        sw [threadIdx.x] = g_w [b][threadIdx.x];
    }
    __syncthreads();

    const size_t base   = (size_t)b * NCHUNK;
    const int    stride = gridDim.x * blockDim.x;
    const int    iters  = NCHUNK / stride;     // exact

    // reversed traversal: first iterations touch pass1's L2-resident tail
    int m = (NCHUNK - 1) - (blockIdx.x * blockDim.x + threadIdx.x);
    int4   iv = inst[base + m];
    float4 tv = tmk [base + m];
    const float4* ep = emb + ((base + (size_t)m) << 2);
    float4 e0 = ep[0], e1 = ep[1], e2 = ep[2], e3 = ep[3];

    float acc0 = 0.f, acc1 = 0.f;
    for (int it = 1; it < iters; it++) {
        const int mn = m - stride;
        int4   ivn = inst[base + mn];
        float4 tvn = tmk [base + mn];
        const float4* en = emb + ((base + (size_t)mn) << 2);
        float4 n0 = en[0], n1 = en[1], n2 = en[2], n3 = en[3];

        PASS2_PX(iv.x, tv.x, e0, acc0);
        PASS2_PX(iv.y, tv.y, e1, acc1);
        PASS2_PX(iv.z, tv.z, e2, acc0);
        PASS2_PX(iv.w, tv.w, e3, acc1);

        iv = ivn; tv = tvn;
        e0 = n0; e1 = n1; e2 = n2; e3 = n3;
        m = mn;
    }
    PASS2_PX(iv.x, tv.x, e0, acc0);
    PASS2_PX(iv.y, tv.y, e1, acc1);
    PASS2_PX(iv.z, tv.z, e2, acc0);
    PASS2_PX(iv.w, tv.w, e3, acc1);

    float v = wredf(acc0 + acc1);
    if ((threadIdx.x & 31u) == 0) atomicAdd(&g_loss, v);
}

// ---------------- finalize ---------------------------------------------------
__global__ void k_fin(float* out) {
    if (threadIdx.x == 0) {
        float misc = 0.f;
        for (int b = 0; b < NBATCH; b++) misc += g_misc[b];
        out[0] = g_loss + misc * (1.0f / 16.0f);
    }
}

// ---------------- launch -----------------------------------------------------
static int pick_gx(int occ, int nsm) {
    const int divs[8] = {80, 50, 40, 25, 20, 16, 10, 8};  // divisors of 400
    int slots = (occ < 1 ? 1 : occ) * nsm;
    for (int i = 0; i < 8; i++)
        if (NBATCH * divs[i] <= slots) return divs[i];
    return 8;
}

extern "C" void kernel_launch(void* const* d_in, const int* in_sizes, int n_in,
                              void* d_out, int out_size) {
    (void)in_sizes; (void)n_in; (void)out_size;
    const float4* emb  = (const float4*)d_in[0];
    const int4*   inst = (const int4*)  d_in[1];
    const float4* ker  = (const float4*)d_in[2];
    const float4* tmk  = (const float4*)d_in[3];
    float*        out  = (float*)d_out;

    int nsm = 152;
    cudaDeviceGetAttribute(&nsm, cudaDevAttrMultiProcessorCount, 0);
    int occ1 = 0, occ2 = 0;
    cudaOccupancyMaxActiveBlocksPerMultiprocessor(&occ1, k_pass1, 256, 0);
    cudaOccupancyMaxActiveBlocksPerMultiprocessor(&occ2, k_pass2, 256, 0);
    int gx1 = pick_gx(occ1, nsm);
    int gx2 = pick_gx(occ2, nsm);

    k_zero<<<1, 512>>>();
    k_pass1<<<dim3(gx1, NBATCH), 256>>>(emb, inst, ker, tmk);
    k_mid<<<1, 128>>>();
    k_pass2<<<dim3(gx2, NBATCH), 256>>>(emb, inst, tmk);
    k_fin<<<1, 32>>>(out);
}